// round 3
// baseline (speedup 1.0000x reference)
#include <cuda_runtime.h>
#include <cuda_bf16.h>

// Problem constants
#define Bq 2
#define Sq 2048
#define Dq 1024
#define Hq 16
#define HDq 64
#define Mq (Bq * Sq)   // 4096

// Scratch (device globals: allocation-free)
__device__ float g_q[Bq * Hq * Sq * HDq];    // [b][h][s][hd]
__device__ float g_k[Bq * Hq * Sq * HDq];
__device__ float g_v[Bq * Hq * Sq * HDq];
__device__ float g_att[Mq * Dq];             // [b*s][d]  (d = h*64+hd)

// ---------------------------------------------------------------------------
// Tiled fp32 GEMM, NT form: C[m,n] = sum_k A[m,k] * W[n,k] + bias[n]
// BM=BN=64, BK=16, 256 threads, 4x4 microtile per thread.
// head_major==1: write C to [b][h][s][hd] layout (for QKV projections).
// head_major==0: write C row-major [m][n] (for attention output projection).
// ---------------------------------------------------------------------------
__global__ __launch_bounds__(256) void gemm_nt(
    const float* __restrict__ A, const float* __restrict__ W,
    const float* __restrict__ bias, float* __restrict__ C,
    int K, int N, int head_major)
{
    __shared__ float As[16][64];
    __shared__ float Bs[16][64];

    const int tx = threadIdx.x & 15;        // 0..15 -> n
    const int ty = threadIdx.x >> 4;        // 0..15 -> m
    const int m0 = blockIdx.y * 64;
    const int n0 = blockIdx.x * 64;

    float acc[4][4] = {};

    const int t   = threadIdx.x;
    const int row = t >> 2;                 // 0..63
    const int kc  = (t & 3) * 4;            // 0,4,8,12

    for (int k0 = 0; k0 < K; k0 += 16) {
        // Load A tile [64 x 16] and W tile [64 x 16], store k-major in shared
        float4 a = *(const float4*)(A + (size_t)(m0 + row) * K + k0 + kc);
        float4 b = *(const float4*)(W + (size_t)(n0 + row) * K + k0 + kc);
        As[kc + 0][row] = a.x; As[kc + 1][row] = a.y;
        As[kc + 2][row] = a.z; As[kc + 3][row] = a.w;
        Bs[kc + 0][row] = b.x; Bs[kc + 1][row] = b.y;
        Bs[kc + 2][row] = b.z; Bs[kc + 3][row] = b.w;
        __syncthreads();

        #pragma unroll
        for (int kk = 0; kk < 16; kk++) {
            float4 av = *(const float4*)&As[kk][ty * 4];
            float4 bv = *(const float4*)&Bs[kk][tx * 4];
            float am[4] = {av.x, av.y, av.z, av.w};
            float bm[4] = {bv.x, bv.y, bv.z, bv.w};
            #pragma unroll
            for (int i = 0; i < 4; i++)
                #pragma unroll
                for (int j = 0; j < 4; j++)
                    acc[i][j] += am[i] * bm[j];
        }
        __syncthreads();
    }

    #pragma unroll
    for (int i = 0; i < 4; i++) {
        int m = m0 + ty * 4 + i;
        #pragma unroll
        for (int j = 0; j < 4; j++) {
            int n = n0 + tx * 4 + j;
            float val = acc[i][j] + bias[n];
            if (head_major) {
                int bb = m >> 11;           // m / 2048
                int ss = m & 2047;
                int hh = n >> 6;            // n / 64
                int hd = n & 63;
                C[((((size_t)bb * Hq + hh) << 11) + ss) * HDq + hd] = val;
            } else {
                C[(size_t)m * N + n] = val;
            }
        }
    }
}

// ---------------------------------------------------------------------------
// Flash attention: one thread per query row, 128 rows/block, one (b,h) per
// blockIdx.y. K/V tiles of 64 keys staged in shared memory (float4).
// Online softmax with branch-guarded rescale. Output in [b*s][h*64+hd].
// ---------------------------------------------------------------------------
__global__ __launch_bounds__(128) void attn_kernel()
{
    const int bh  = blockIdx.y;                 // 0..31
    const int row = blockIdx.x * 128 + threadIdx.x;   // query index s, 0..2047
    const int b   = bh >> 4;
    const int h   = bh & 15;

    const float4* q4 = (const float4*)g_q;
    const float4* k4 = (const float4*)g_k;
    const float4* v4 = (const float4*)g_v;

    // Load q row, pre-scale by 1/sqrt(HD) = 0.125
    float4 qr[16];
    {
        size_t base = ((size_t)bh * Sq + row) * (HDq / 4);
        #pragma unroll
        for (int c = 0; c < 16; c++) {
            float4 v = q4[base + c];
            v.x *= 0.125f; v.y *= 0.125f; v.z *= 0.125f; v.w *= 0.125f;
            qr[c] = v;
        }
    }

    float4 o[16];
    #pragma unroll
    for (int c = 0; c < 16; c++) o[c] = make_float4(0.f, 0.f, 0.f, 0.f);
    float mmax = -1e30f;
    float lsum = 0.f;

    __shared__ float4 ks[64][16];
    __shared__ float4 vs[64][16];

    for (int tile = 0; tile < Sq / 64; tile++) {
        __syncthreads();
        // cooperative load of 64 keys + 64 values (1024 float4 each)
        size_t gbase = ((size_t)bh * Sq + tile * 64) * (HDq / 4);
        #pragma unroll
        for (int i = 0; i < 8; i++) {
            int idx = i * 128 + threadIdx.x;    // 0..1023
            int key = idx >> 4;
            int c   = idx & 15;
            ks[key][c] = k4[gbase + idx];
            vs[key][c] = v4[gbase + idx];
        }
        __syncthreads();

        for (int j = 0; j < 64; j++) {
            float s = 0.f;
            #pragma unroll
            for (int c = 0; c < 16; c++) {
                float4 kv = ks[j][c];
                s += qr[c].x * kv.x + qr[c].y * kv.y
                   + qr[c].z * kv.z + qr[c].w * kv.w;
            }
            if (s > mmax) {
                float alpha = __expf(mmax - s);
                mmax = s;
                lsum *= alpha;
                #pragma unroll
                for (int c = 0; c < 16; c++) {
                    o[c].x *= alpha; o[c].y *= alpha;
                    o[c].z *= alpha; o[c].w *= alpha;
                }
            }
            float p = __expf(s - mmax);
            lsum += p;
            #pragma unroll
            for (int c = 0; c < 16; c++) {
                float4 vv = vs[j][c];
                o[c].x += p * vv.x; o[c].y += p * vv.y;
                o[c].z += p * vv.z; o[c].w += p * vv.w;
            }
        }
    }

    float inv = 1.0f / lsum;
    float4* out4 = (float4*)g_att;
    size_t obase = ((size_t)(b * Sq + row) * Dq + h * HDq) / 4;
    #pragma unroll
    for (int c = 0; c < 16; c++) {
        float4 v = o[c];
        v.x *= inv; v.y *= inv; v.z *= inv; v.w *= inv;
        out4[obase + c] = v;
    }
}

// ---------------------------------------------------------------------------
// Launch
// Input order (metadata): xq, xv, xk, Wq, bq, Wk, bk, Wv, bv, Wo, bo
// ---------------------------------------------------------------------------
extern "C" void kernel_launch(void* const* d_in, const int* in_sizes, int n_in,
                              void* d_out, int out_size)
{
    const float* xq = (const float*)d_in[0];
    const float* xv = (const float*)d_in[1];
    const float* xk = (const float*)d_in[2];
    const float* Wq = (const float*)d_in[3];
    const float* bq = (const float*)d_in[4];
    const float* Wk = (const float*)d_in[5];
    const float* bk = (const float*)d_in[6];
    const float* Wv = (const float*)d_in[7];
    const float* bv = (const float*)d_in[8];
    const float* Wo = (const float*)d_in[9];
    const float* bo = (const float*)d_in[10];
    float* out = (float*)d_out;

    float *pq, *pk, *pv, *patt;
    cudaGetSymbolAddress((void**)&pq, g_q);
    cudaGetSymbolAddress((void**)&pk, g_k);
    cudaGetSymbolAddress((void**)&pv, g_v);
    cudaGetSymbolAddress((void**)&patt, g_att);

    dim3 gproj(Dq / 64, Mq / 64);   // (16, 64)
    gemm_nt<<<gproj, 256>>>(xq, Wq, bq, pq, Dq, Dq, 1);
    gemm_nt<<<gproj, 256>>>(xk, Wk, bk, pk, Dq, Dq, 1);
    gemm_nt<<<gproj, 256>>>(xv, Wv, bv, pv, Dq, Dq, 1);

    dim3 gattn(Sq / 128, Bq * Hq);  // (16, 32)
    attn_kernel<<<gattn, 128>>>();

    gemm_nt<<<gproj, 256>>>(patt, Wo, bo, out, Dq, Dq, 0);
}

// round 4
// speedup vs baseline: 1.3666x; 1.3666x over previous
#include <cuda_runtime.h>
#include <cuda_bf16.h>

// Problem constants
#define Bq 2
#define Sq 2048
#define Dq 1024
#define Hq 16
#define HDq 64
#define Mq (Bq * Sq)   // 4096
#define GK Dq          // 1024 (GEMM K and N)

// Scratch (device globals: allocation-free)
__device__ float g_q[Bq * Hq * Sq * HDq];    // [b][h][s][hd]
__device__ float g_k[Bq * Hq * Sq * HDq];
__device__ float g_v[Bq * Hq * Sq * HDq];
__device__ float g_att[Mq * Dq];             // [b*s][d]  (d = h*64+hd)

// ---------------------------------------------------------------------------
// TF32 helpers
// ---------------------------------------------------------------------------
__device__ __forceinline__ float tf32r(float x) {
    unsigned u;
    asm("cvt.rna.tf32.f32 %0, %1;" : "=r"(u) : "f"(x));
    return __uint_as_float(u);
}

__device__ __forceinline__ void mma_tf32(float c[4], const unsigned a[4],
                                         const unsigned b[2]) {
    asm volatile(
        "mma.sync.aligned.m16n8k8.row.col.f32.tf32.tf32.f32 "
        "{%0,%1,%2,%3}, {%4,%5,%6,%7}, {%8,%9}, {%0,%1,%2,%3};\n"
        : "+f"(c[0]), "+f"(c[1]), "+f"(c[2]), "+f"(c[3])
        : "r"(a[0]), "r"(a[1]), "r"(a[2]), "r"(a[3]),
          "r"(b[0]), "r"(b[1]));
}

// ---------------------------------------------------------------------------
// TF32 tensor-core GEMM, NT form: C[m,n] = sum_k A[m,k] * W[n,k] + bias[n]
// BM=128, BN=128, BK=32. 256 threads = 8 warps (4 m x 2 n), each warp 32x64
// via m16n8k8 tf32 mma.sync. head_major selects output layout.
// ---------------------------------------------------------------------------
#define LDS_ST 36   // padded row stride (floats): bank = (4*row + col) % 32

__global__ __launch_bounds__(256) void gemm_tf32(
    const float* __restrict__ A, const float* __restrict__ W,
    const float* __restrict__ bias, float* __restrict__ C,
    int head_major)
{
    __shared__ float As[128][LDS_ST];
    __shared__ float Ws[128][LDS_ST];

    const int tid  = threadIdx.x;
    const int warp = tid >> 5;
    const int lane = tid & 31;
    const int g    = lane >> 2;     // 0..7
    const int t    = lane & 3;      // 0..3
    const int wm   = (warp >> 1) * 32;   // warp m offset in tile
    const int wn   = (warp & 1) * 64;    // warp n offset in tile
    const int m0   = blockIdx.y * 128;
    const int n0   = blockIdx.x * 128;

    float acc[2][8][4] = {};

    for (int k0 = 0; k0 < GK; k0 += 32) {
        // Stage A/W tiles (128x32), converting to tf32 (rna)
        #pragma unroll
        for (int i = 0; i < 4; i++) {
            int idx = tid + i * 256;     // 0..1023
            int r   = idx >> 3;          // 0..127
            int c   = (idx & 7) * 4;     // 0..28
            float4 a = *(const float4*)(A + (size_t)(m0 + r) * GK + k0 + c);
            float4 w = *(const float4*)(W + (size_t)(n0 + r) * GK + k0 + c);
            float4 at = make_float4(tf32r(a.x), tf32r(a.y), tf32r(a.z), tf32r(a.w));
            float4 wt = make_float4(tf32r(w.x), tf32r(w.y), tf32r(w.z), tf32r(w.w));
            *(float4*)&As[r][c] = at;
            *(float4*)&Ws[r][c] = wt;
        }
        __syncthreads();

        #pragma unroll
        for (int ks = 0; ks < 32; ks += 8) {
            unsigned af[2][4];
            unsigned bf[8][2];
            #pragma unroll
            for (int i = 0; i < 2; i++) {
                int r = wm + i * 16 + g;
                af[i][0] = __float_as_uint(As[r][ks + t]);
                af[i][1] = __float_as_uint(As[r + 8][ks + t]);
                af[i][2] = __float_as_uint(As[r][ks + t + 4]);
                af[i][3] = __float_as_uint(As[r + 8][ks + t + 4]);
            }
            #pragma unroll
            for (int j = 0; j < 8; j++) {
                int r = wn + j * 8 + g;
                bf[j][0] = __float_as_uint(Ws[r][ks + t]);
                bf[j][1] = __float_as_uint(Ws[r][ks + t + 4]);
            }
            #pragma unroll
            for (int i = 0; i < 2; i++)
                #pragma unroll
                for (int j = 0; j < 8; j++)
                    mma_tf32(acc[i][j], af[i], bf[j]);
        }
        __syncthreads();
    }

    // Epilogue: c0 (g, 2t), c1 (g, 2t+1), c2 (g+8, 2t), c3 (g+8, 2t+1)
    #pragma unroll
    for (int i = 0; i < 2; i++) {
        #pragma unroll
        for (int j = 0; j < 8; j++) {
            int mrow = m0 + wm + i * 16 + g;
            int ncol = n0 + wn + j * 8 + t * 2;
            float b0 = bias[ncol], b1 = bias[ncol + 1];
            float2 lo = make_float2(acc[i][j][0] + b0, acc[i][j][1] + b1);
            float2 hi = make_float2(acc[i][j][2] + b0, acc[i][j][3] + b1);
            if (head_major) {
                int hh = ncol >> 6, hd = ncol & 63;
                size_t a0 = ((((size_t)(mrow >> 11) * Hq + hh) << 11)
                             + (mrow & 2047)) * HDq + hd;
                int mr2 = mrow + 8;
                size_t a1 = ((((size_t)(mr2 >> 11) * Hq + hh) << 11)
                             + (mr2 & 2047)) * HDq + hd;
                *(float2*)(C + a0) = lo;
                *(float2*)(C + a1) = hi;
            } else {
                *(float2*)(C + (size_t)mrow * GK + ncol) = lo;
                *(float2*)(C + (size_t)(mrow + 8) * GK + ncol) = hi;
            }
        }
    }
}

// ---------------------------------------------------------------------------
// Flash attention: one thread per query row, 128 rows/block, one (b,h) per
// blockIdx.y. K/V tiles of 64 keys in shared memory. Online softmax.
// Score dot product uses 4 independent accumulator chains (latency fix).
// ---------------------------------------------------------------------------
__global__ __launch_bounds__(128) void attn_kernel()
{
    const int bh  = blockIdx.y;                       // 0..31
    const int row = blockIdx.x * 128 + threadIdx.x;   // query index
    const int b   = bh >> 4;
    const int h   = bh & 15;

    const float4* q4 = (const float4*)g_q;
    const float4* k4 = (const float4*)g_k;
    const float4* v4 = (const float4*)g_v;

    float4 qr[16];
    {
        size_t base = ((size_t)bh * Sq + row) * (HDq / 4);
        #pragma unroll
        for (int c = 0; c < 16; c++) {
            float4 v = q4[base + c];
            v.x *= 0.125f; v.y *= 0.125f; v.z *= 0.125f; v.w *= 0.125f;
            qr[c] = v;
        }
    }

    float4 o[16];
    #pragma unroll
    for (int c = 0; c < 16; c++) o[c] = make_float4(0.f, 0.f, 0.f, 0.f);
    float mmax = -1e30f;
    float lsum = 0.f;

    __shared__ float4 ks[64][16];
    __shared__ float4 vs[64][16];

    for (int tile = 0; tile < Sq / 64; tile++) {
        __syncthreads();
        size_t gbase = ((size_t)bh * Sq + tile * 64) * (HDq / 4);
        #pragma unroll
        for (int i = 0; i < 8; i++) {
            int idx = i * 128 + threadIdx.x;
            int key = idx >> 4;
            int c   = idx & 15;
            ks[key][c] = k4[gbase + idx];
            vs[key][c] = v4[gbase + idx];
        }
        __syncthreads();

        for (int j = 0; j < 64; j++) {
            // 4 independent FFMA chains for the score
            float s0 = 0.f, s1 = 0.f, s2 = 0.f, s3 = 0.f;
            #pragma unroll
            for (int c = 0; c < 16; c++) {
                float4 kv = ks[j][c];
                s0 += qr[c].x * kv.x;
                s1 += qr[c].y * kv.y;
                s2 += qr[c].z * kv.z;
                s3 += qr[c].w * kv.w;
            }
            float s = (s0 + s1) + (s2 + s3);

            if (s > mmax) {
                float alpha = __expf(mmax - s);
                mmax = s;
                lsum *= alpha;
                #pragma unroll
                for (int c = 0; c < 16; c++) {
                    o[c].x *= alpha; o[c].y *= alpha;
                    o[c].z *= alpha; o[c].w *= alpha;
                }
            }
            float p = __expf(s - mmax);
            lsum += p;
            #pragma unroll
            for (int c = 0; c < 16; c++) {
                float4 vv = vs[j][c];
                o[c].x += p * vv.x; o[c].y += p * vv.y;
                o[c].z += p * vv.z; o[c].w += p * vv.w;
            }
        }
    }

    float inv = 1.0f / lsum;
    float4* out4 = (float4*)g_att;
    size_t obase = ((size_t)(b * Sq + row) * Dq + h * HDq) / 4;
    #pragma unroll
    for (int c = 0; c < 16; c++) {
        float4 v = o[c];
        v.x *= inv; v.y *= inv; v.z *= inv; v.w *= inv;
        out4[obase + c] = v;
    }
}

// ---------------------------------------------------------------------------
// Launch.  Input order: xq, xv, xk, Wq, bq, Wk, bk, Wv, bv, Wo, bo
// ---------------------------------------------------------------------------
extern "C" void kernel_launch(void* const* d_in, const int* in_sizes, int n_in,
                              void* d_out, int out_size)
{
    const float* xq = (const float*)d_in[0];
    const float* xv = (const float*)d_in[1];
    const float* xk = (const float*)d_in[2];
    const float* Wq = (const float*)d_in[3];
    const float* bq = (const float*)d_in[4];
    const float* Wk = (const float*)d_in[5];
    const float* bk = (const float*)d_in[6];
    const float* Wv = (const float*)d_in[7];
    const float* bv = (const float*)d_in[8];
    const float* Wo = (const float*)d_in[9];
    const float* bo = (const float*)d_in[10];
    float* out = (float*)d_out;

    float *pq, *pk, *pv, *patt;
    cudaGetSymbolAddress((void**)&pq, g_q);
    cudaGetSymbolAddress((void**)&pk, g_k);
    cudaGetSymbolAddress((void**)&pv, g_v);
    cudaGetSymbolAddress((void**)&patt, g_att);

    dim3 gproj(Dq / 128, Mq / 128);   // (8, 32)
    gemm_tf32<<<gproj, 256>>>(xq, Wq, bq, pq, 1);
    gemm_tf32<<<gproj, 256>>>(xk, Wk, bk, pk, 1);
    gemm_tf32<<<gproj, 256>>>(xv, Wv, bv, pv, 1);

    dim3 gattn(Sq / 128, Bq * Hq);    // (16, 32)
    attn_kernel<<<gattn, 128>>>();

    gemm_tf32<<<gproj, 256>>>(patt, Wo, bo, out, 0);
}

// round 5
// speedup vs baseline: 3.0151x; 2.2063x over previous
#include <cuda_runtime.h>
#include <cuda_bf16.h>

// Problem constants
#define Bq 2
#define Sq 2048
#define Dq 1024
#define Hq 16
#define HDq 64
#define Mq (Bq * Sq)   // 4096
#define GK Dq          // 1024 (GEMM K and N)

// Scratch (device globals: allocation-free)
__device__ float g_q[Bq * Hq * Sq * HDq];    // [b][h][s][hd]
__device__ float g_k[Bq * Hq * Sq * HDq];
__device__ float g_v[Bq * Hq * Sq * HDq];
__device__ float g_att[Mq * Dq];             // [b*s][d]  (d = h*64+hd)

// ---------------------------------------------------------------------------
// TF32 helpers
// ---------------------------------------------------------------------------
__device__ __forceinline__ float tf32r(float x) {
    unsigned u;
    asm("cvt.rna.tf32.f32 %0, %1;" : "=r"(u) : "f"(x));
    return __uint_as_float(u);
}

__device__ __forceinline__ void mma_tf32(float c[4], const unsigned a[4],
                                         const unsigned b[2]) {
    asm volatile(
        "mma.sync.aligned.m16n8k8.row.col.f32.tf32.tf32.f32 "
        "{%0,%1,%2,%3}, {%4,%5,%6,%7}, {%8,%9}, {%0,%1,%2,%3};\n"
        : "+f"(c[0]), "+f"(c[1]), "+f"(c[2]), "+f"(c[3])
        : "r"(a[0]), "r"(a[1]), "r"(a[2]), "r"(a[3]),
          "r"(b[0]), "r"(b[1]));
}

// ---------------------------------------------------------------------------
// TF32 tensor-core GEMM, NT form: C[m,n] = sum_k A[m,k] * W[n,k] + bias[n]
// BM=128, BN=128, BK=32. 256 threads = 8 warps (4 m x 2 n), each warp 32x64.
// ---------------------------------------------------------------------------
#define LDS_ST 36

__global__ __launch_bounds__(256) void gemm_tf32(
    const float* __restrict__ A, const float* __restrict__ W,
    const float* __restrict__ bias, float* __restrict__ C,
    int head_major)
{
    __shared__ float As[128][LDS_ST];
    __shared__ float Ws[128][LDS_ST];

    const int tid  = threadIdx.x;
    const int warp = tid >> 5;
    const int lane = tid & 31;
    const int g    = lane >> 2;
    const int t    = lane & 3;
    const int wm   = (warp >> 1) * 32;
    const int wn   = (warp & 1) * 64;
    const int m0   = blockIdx.y * 128;
    const int n0   = blockIdx.x * 128;

    float acc[2][8][4] = {};

    for (int k0 = 0; k0 < GK; k0 += 32) {
        #pragma unroll
        for (int i = 0; i < 4; i++) {
            int idx = tid + i * 256;
            int r   = idx >> 3;
            int c   = (idx & 7) * 4;
            float4 a = *(const float4*)(A + (size_t)(m0 + r) * GK + k0 + c);
            float4 w = *(const float4*)(W + (size_t)(n0 + r) * GK + k0 + c);
            float4 at = make_float4(tf32r(a.x), tf32r(a.y), tf32r(a.z), tf32r(a.w));
            float4 wt = make_float4(tf32r(w.x), tf32r(w.y), tf32r(w.z), tf32r(w.w));
            *(float4*)&As[r][c] = at;
            *(float4*)&Ws[r][c] = wt;
        }
        __syncthreads();

        #pragma unroll
        for (int ks = 0; ks < 32; ks += 8) {
            unsigned af[2][4];
            unsigned bf[8][2];
            #pragma unroll
            for (int i = 0; i < 2; i++) {
                int r = wm + i * 16 + g;
                af[i][0] = __float_as_uint(As[r][ks + t]);
                af[i][1] = __float_as_uint(As[r + 8][ks + t]);
                af[i][2] = __float_as_uint(As[r][ks + t + 4]);
                af[i][3] = __float_as_uint(As[r + 8][ks + t + 4]);
            }
            #pragma unroll
            for (int j = 0; j < 8; j++) {
                int r = wn + j * 8 + g;
                bf[j][0] = __float_as_uint(Ws[r][ks + t]);
                bf[j][1] = __float_as_uint(Ws[r][ks + t + 4]);
            }
            #pragma unroll
            for (int i = 0; i < 2; i++)
                #pragma unroll
                for (int j = 0; j < 8; j++)
                    mma_tf32(acc[i][j], af[i], bf[j]);
        }
        __syncthreads();
    }

    #pragma unroll
    for (int i = 0; i < 2; i++) {
        #pragma unroll
        for (int j = 0; j < 8; j++) {
            int mrow = m0 + wm + i * 16 + g;
            int ncol = n0 + wn + j * 8 + t * 2;
            float b0 = bias[ncol], b1 = bias[ncol + 1];
            float2 lo = make_float2(acc[i][j][0] + b0, acc[i][j][1] + b1);
            float2 hi = make_float2(acc[i][j][2] + b0, acc[i][j][3] + b1);
            if (head_major) {
                int hh = ncol >> 6, hd = ncol & 63;
                size_t a0 = ((((size_t)(mrow >> 11) * Hq + hh) << 11)
                             + (mrow & 2047)) * HDq + hd;
                int mr2 = mrow + 8;
                size_t a1 = ((((size_t)(mr2 >> 11) * Hq + hh) << 11)
                             + (mr2 & 2047)) * HDq + hd;
                *(float2*)(C + a0) = lo;
                *(float2*)(C + a1) = hi;
            } else {
                *(float2*)(C + (size_t)mrow * GK + ncol) = lo;
                *(float2*)(C + (size_t)(mrow + 8) * GK + ncol) = hi;
            }
        }
    }
}

// ---------------------------------------------------------------------------
// Tensor-core flash attention (TF32 mma.sync).
// Block: 64 queries of one (b,h); 4 warps (16 query rows each).
// Loop over 32 key tiles of 64. Q held as register A-fragments.
// K tile smem buffer is reused for P (accumulator->A-operand round trip).
// ---------------------------------------------------------------------------
#define AT_ST 68   // smem row stride (floats): bank(row,col) = (4*row+col)%32

__global__ __launch_bounds__(128) void attn_mma()
{
    const int bh   = blockIdx.y;          // 0..31
    const int q0   = blockIdx.x * 64;     // query tile base
    const int b    = bh >> 4;
    const int h    = bh & 15;
    const int tid  = threadIdx.x;
    const int warp = tid >> 5;
    const int lane = tid & 31;
    const int g    = lane >> 2;           // 0..7
    const int t    = lane & 3;            // 0..3
    const int wm   = warp * 16;           // warp's query-row offset in tile

    __shared__ float Ks[64][AT_ST];       // K tile, then P tile
    __shared__ float Vs[64][AT_ST];       // V tile [key][hd]

    const float* gq = g_q + (((size_t)bh) << 11) * HDq;
    const float* gk = g_k + (((size_t)bh) << 11) * HDq;
    const float* gv = g_v + (((size_t)bh) << 11) * HDq;

    // Stage Q tile through smem, extract register A-fragments (scaled, tf32)
    {
        const float4* src = (const float4*)(gq + (size_t)q0 * HDq);
        #pragma unroll
        for (int i = 0; i < 8; i++) {
            int idx = i * 128 + tid;
            int r = idx >> 4, c = (idx & 15) * 4;
            float4 v = src[idx];
            v.x = tf32r(v.x * 0.125f); v.y = tf32r(v.y * 0.125f);
            v.z = tf32r(v.z * 0.125f); v.w = tf32r(v.w * 0.125f);
            *(float4*)&Ks[r][c] = v;
        }
    }
    __syncthreads();
    unsigned qa[8][4];
    #pragma unroll
    for (int k = 0; k < 8; k++) {
        qa[k][0] = __float_as_uint(Ks[wm + g][k * 8 + t]);
        qa[k][1] = __float_as_uint(Ks[wm + g + 8][k * 8 + t]);
        qa[k][2] = __float_as_uint(Ks[wm + g][k * 8 + t + 4]);
        qa[k][3] = __float_as_uint(Ks[wm + g + 8][k * 8 + t + 4]);
    }
    __syncthreads();

    float oacc[8][4] = {};
    float m0 = -1e30f, m1 = -1e30f, l0 = 0.f, l1 = 0.f;

    for (int tile = 0; tile < Sq / 64; tile++) {
        // Stage K and V tiles (tf32-rounded)
        const float4* ksrc = (const float4*)(gk + (size_t)tile * 64 * HDq);
        const float4* vsrc = (const float4*)(gv + (size_t)tile * 64 * HDq);
        #pragma unroll
        for (int i = 0; i < 8; i++) {
            int idx = i * 128 + tid;
            int r = idx >> 4, c = (idx & 15) * 4;
            float4 kv = ksrc[idx];
            float4 vv = vsrc[idx];
            kv.x = tf32r(kv.x); kv.y = tf32r(kv.y);
            kv.z = tf32r(kv.z); kv.w = tf32r(kv.w);
            vv.x = tf32r(vv.x); vv.y = tf32r(vv.y);
            vv.z = tf32r(vv.z); vv.w = tf32r(vv.w);
            *(float4*)&Ks[r][c] = kv;
            *(float4*)&Vs[r][c] = vv;
        }
        __syncthreads();

        // S = Q K^T  (per warp: 16 x 64)
        float sacc[8][4] = {};
        #pragma unroll
        for (int k = 0; k < 8; k++) {
            #pragma unroll
            for (int j = 0; j < 8; j++) {
                unsigned bf[2];
                bf[0] = __float_as_uint(Ks[j * 8 + g][k * 8 + t]);
                bf[1] = __float_as_uint(Ks[j * 8 + g][k * 8 + t + 4]);
                mma_tf32(sacc[j], qa[k], bf);
            }
        }

        // Online softmax on fragments. Row r0 = wm+g (c0,c1), r1 = r0+8 (c2,c3).
        float mx0 = -1e30f, mx1 = -1e30f;
        #pragma unroll
        for (int j = 0; j < 8; j++) {
            mx0 = fmaxf(mx0, fmaxf(sacc[j][0], sacc[j][1]));
            mx1 = fmaxf(mx1, fmaxf(sacc[j][2], sacc[j][3]));
        }
        mx0 = fmaxf(mx0, __shfl_xor_sync(0xffffffffu, mx0, 1));
        mx0 = fmaxf(mx0, __shfl_xor_sync(0xffffffffu, mx0, 2));
        mx1 = fmaxf(mx1, __shfl_xor_sync(0xffffffffu, mx1, 1));
        mx1 = fmaxf(mx1, __shfl_xor_sync(0xffffffffu, mx1, 2));

        float nm0 = fmaxf(m0, mx0), nm1 = fmaxf(m1, mx1);
        float a0 = __expf(m0 - nm0), a1 = __expf(m1 - nm1);
        m0 = nm0; m1 = nm1;

        float ps0 = 0.f, ps1 = 0.f;
        #pragma unroll
        for (int j = 0; j < 8; j++) {
            sacc[j][0] = __expf(sacc[j][0] - m0);
            sacc[j][1] = __expf(sacc[j][1] - m0);
            sacc[j][2] = __expf(sacc[j][2] - m1);
            sacc[j][3] = __expf(sacc[j][3] - m1);
            ps0 += sacc[j][0] + sacc[j][1];
            ps1 += sacc[j][2] + sacc[j][3];
        }
        ps0 += __shfl_xor_sync(0xffffffffu, ps0, 1);
        ps0 += __shfl_xor_sync(0xffffffffu, ps0, 2);
        ps1 += __shfl_xor_sync(0xffffffffu, ps1, 1);
        ps1 += __shfl_xor_sync(0xffffffffu, ps1, 2);
        l0 = l0 * a0 + ps0;
        l1 = l1 * a1 + ps1;

        #pragma unroll
        for (int j = 0; j < 8; j++) {
            oacc[j][0] *= a0; oacc[j][1] *= a0;
            oacc[j][2] *= a1; oacc[j][3] *= a1;
        }

        __syncthreads();   // all warps finished reading Ks (S mma)

        // Store P (tf32) into the K buffer, [query row][key]
        #pragma unroll
        for (int j = 0; j < 8; j++) {
            *(float2*)&Ks[wm + g][j * 8 + 2 * t] =
                make_float2(tf32r(sacc[j][0]), tf32r(sacc[j][1]));
            *(float2*)&Ks[wm + g + 8][j * 8 + 2 * t] =
                make_float2(tf32r(sacc[j][2]), tf32r(sacc[j][3]));
        }
        __syncthreads();

        // O += P V   (per warp: 16 x 64, K = 64 keys)
        #pragma unroll
        for (int k = 0; k < 8; k++) {
            unsigned pa[4];
            pa[0] = __float_as_uint(Ks[wm + g][k * 8 + t]);
            pa[1] = __float_as_uint(Ks[wm + g + 8][k * 8 + t]);
            pa[2] = __float_as_uint(Ks[wm + g][k * 8 + t + 4]);
            pa[3] = __float_as_uint(Ks[wm + g + 8][k * 8 + t + 4]);
            #pragma unroll
            for (int j = 0; j < 8; j++) {
                unsigned bf[2];
                bf[0] = __float_as_uint(Vs[k * 8 + t][j * 8 + g]);
                bf[1] = __float_as_uint(Vs[k * 8 + t + 4][j * 8 + g]);
                mma_tf32(oacc[j], pa, bf);
            }
        }
        __syncthreads();   // before next tile overwrites Ks/Vs
    }

    // Epilogue: O /= l, write to g_att [b*s][h*64+hd]
    float il0 = 1.0f / l0, il1 = 1.0f / l1;
    #pragma unroll
    for (int j = 0; j < 8; j++) {
        int r0 = q0 + wm + g;
        int col = h * HDq + j * 8 + 2 * t;
        size_t a0 = (size_t)(b * Sq + r0) * Dq + col;
        size_t a1 = (size_t)(b * Sq + r0 + 8) * Dq + col;
        *(float2*)(g_att + a0) = make_float2(oacc[j][0] * il0, oacc[j][1] * il0);
        *(float2*)(g_att + a1) = make_float2(oacc[j][2] * il1, oacc[j][3] * il1);
    }
}

// ---------------------------------------------------------------------------
// Launch.  Input order: xq, xv, xk, Wq, bq, Wk, bk, Wv, bv, Wo, bo
// ---------------------------------------------------------------------------
extern "C" void kernel_launch(void* const* d_in, const int* in_sizes, int n_in,
                              void* d_out, int out_size)
{
    const float* xq = (const float*)d_in[0];
    const float* xv = (const float*)d_in[1];
    const float* xk = (const float*)d_in[2];
    const float* Wq = (const float*)d_in[3];
    const float* bq = (const float*)d_in[4];
    const float* Wk = (const float*)d_in[5];
    const float* bk = (const float*)d_in[6];
    const float* Wv = (const float*)d_in[7];
    const float* bv = (const float*)d_in[8];
    const float* Wo = (const float*)d_in[9];
    const float* bo = (const float*)d_in[10];
    float* out = (float*)d_out;

    float *pq, *pk, *pv, *patt;
    cudaGetSymbolAddress((void**)&pq, g_q);
    cudaGetSymbolAddress((void**)&pk, g_k);
    cudaGetSymbolAddress((void**)&pv, g_v);
    cudaGetSymbolAddress((void**)&patt, g_att);

    dim3 gproj(Dq / 128, Mq / 128);   // (8, 32)
    gemm_tf32<<<gproj, 256>>>(xq, Wq, bq, pq, 1);
    gemm_tf32<<<gproj, 256>>>(xk, Wk, bk, pk, 1);
    gemm_tf32<<<gproj, 256>>>(xv, Wv, bv, pv, 1);

    dim3 gattn(Sq / 64, Bq * Hq);     // (32, 32)
    attn_mma<<<gattn, 128>>>();

    gemm_tf32<<<gproj, 256>>>(patt, Wo, bo, out, 0);
}

// round 7
// speedup vs baseline: 3.8611x; 1.2806x over previous
#include <cuda_runtime.h>
#include <cuda_bf16.h>

// Problem constants
#define Bq 2
#define Sq 2048
#define Dq 1024
#define Hq 16
#define HDq 64
#define Mq (Bq * Sq)   // 4096
#define GK Dq          // 1024

// Scratch (device globals: allocation-free)
__device__ float g_q[Bq * Hq * Sq * HDq];    // [b][h][s][hd]
__device__ float g_k[Bq * Hq * Sq * HDq];
__device__ float g_v[Bq * Hq * Sq * HDq];
__device__ float g_att[Mq * Dq];             // [b*s][d]

// ---------------------------------------------------------------------------
// TF32 helpers
// ---------------------------------------------------------------------------
__device__ __forceinline__ float tf32r(float x) {
    unsigned u;
    asm("cvt.rna.tf32.f32 %0, %1;" : "=r"(u) : "f"(x));
    return __uint_as_float(u);
}
__device__ __forceinline__ unsigned tf32u(float x) {
    unsigned u;
    asm("cvt.rna.tf32.f32 %0, %1;" : "=r"(u) : "f"(x));
    return u;
}

__device__ __forceinline__ void mma_tf32(float c[4], const unsigned a[4],
                                         const unsigned b[2]) {
    asm volatile(
        "mma.sync.aligned.m16n8k8.row.col.f32.tf32.tf32.f32 "
        "{%0,%1,%2,%3}, {%4,%5,%6,%7}, {%8,%9}, {%0,%1,%2,%3};\n"
        : "+f"(c[0]), "+f"(c[1]), "+f"(c[2]), "+f"(c[3])
        : "r"(a[0]), "r"(a[1]), "r"(a[2]), "r"(a[3]),
          "r"(b[0]), "r"(b[1]));
}

// ===========================================================================
// TF32 GEMM, NT: C[m,n] = sum_k A[m,k]*W[n,k] + bias[n]
// BM=BN=128, BK=32, 256 threads, 8 warps (4m x 2n), warp tile 32x64.
// Double-buffered smem, register prefetch. Column layout within each 8-k
// group is interleaved (u -> (u&3)*2 + (u>>2)) so that the (t, t+4)
// fragment pairs are adjacent -> LDS.64, conflict-free with stride 40.
// grid.z selects one of up to 3 independent GEMMs (fused QKV).
// ===========================================================================
#define GST 40
#define GEMM_SMEM (4 * 128 * GST * 4)   // 2 bufs x (A+W) x 128 x GST floats

__global__ __launch_bounds__(256) void gemm_tf32(
    const float* A0, const float* W0, const float* B0, float* C0,
    const float* A1, const float* W1, const float* B1, float* C1,
    const float* A2, const float* W2, const float* B2, float* C2,
    int head_major)
{
    extern __shared__ float sm[];
    // As(buf): sm + buf*128*GST ; Ws(buf): sm + (2+buf)*128*GST
    const float* A; const float* W; const float* bias; float* C;
    if (blockIdx.z == 0)      { A = A0; W = W0; bias = B0; C = C0; }
    else if (blockIdx.z == 1) { A = A1; W = W1; bias = B1; C = C1; }
    else                      { A = A2; W = W2; bias = B2; C = C2; }

    const int tid  = threadIdx.x;
    const int warp = tid >> 5;
    const int lane = tid & 31;
    const int g    = lane >> 2;
    const int t    = lane & 3;
    const int wm   = (warp >> 1) * 32;
    const int wn   = (warp & 1) * 64;
    const int m0   = blockIdx.y * 128;
    const int n0   = blockIdx.x * 128;

    const int r0 = tid >> 2;          // 0..63  (rows r0 and r0+64)
    const int kg = tid & 3;           // k-group 0..3

    float acc[2][8][4] = {};
    float4 ra[2][2], rw[2][2];

    // --- prefetch k0=0 ---
    #pragma unroll
    for (int m = 0; m < 2; m++) {
        const float* pa = A + (size_t)(m0 + r0 + 64 * m) * GK + kg * 8;
        const float* pw = W + (size_t)(n0 + r0 + 64 * m) * GK + kg * 8;
        ra[m][0] = *(const float4*)pa; ra[m][1] = *(const float4*)(pa + 4);
        rw[m][0] = *(const float4*)pw; rw[m][1] = *(const float4*)(pw + 4);
    }
    // store buf 0 (permuted + tf32)
    #pragma unroll
    for (int m = 0; m < 2; m++) {
        float* da = sm + (size_t)(0 * 128 + r0 + 64 * m) * GST + kg * 8;
        float* dw = sm + (size_t)(2 * 128 + r0 + 64 * m) * GST + kg * 8;
        float4 lo = make_float4(tf32r(ra[m][0].x), tf32r(ra[m][1].x),
                                tf32r(ra[m][0].y), tf32r(ra[m][1].y));
        float4 hi = make_float4(tf32r(ra[m][0].z), tf32r(ra[m][1].z),
                                tf32r(ra[m][0].w), tf32r(ra[m][1].w));
        *(float4*)da = lo; *(float4*)(da + 4) = hi;
        lo = make_float4(tf32r(rw[m][0].x), tf32r(rw[m][1].x),
                         tf32r(rw[m][0].y), tf32r(rw[m][1].y));
        hi = make_float4(tf32r(rw[m][0].z), tf32r(rw[m][1].z),
                         tf32r(rw[m][0].w), tf32r(rw[m][1].w));
        *(float4*)dw = lo; *(float4*)(dw + 4) = hi;
    }
    __syncthreads();

    int buf = 0;
    for (int k0 = 0; k0 < GK; k0 += 32) {
        const bool more = (k0 + 32 < GK);
        if (more) {
            #pragma unroll
            for (int m = 0; m < 2; m++) {
                const float* pa = A + (size_t)(m0 + r0 + 64 * m) * GK + k0 + 32 + kg * 8;
                const float* pw = W + (size_t)(n0 + r0 + 64 * m) * GK + k0 + 32 + kg * 8;
                ra[m][0] = *(const float4*)pa; ra[m][1] = *(const float4*)(pa + 4);
                rw[m][0] = *(const float4*)pw; rw[m][1] = *(const float4*)(pw + 4);
            }
        }

        const float* As = sm + (size_t)buf * 128 * GST;
        const float* Ws = sm + (size_t)(2 + buf) * 128 * GST;
        #pragma unroll
        for (int ks = 0; ks < 4; ks++) {
            const int kc = ks * 8 + 2 * t;
            unsigned af[2][4];
            #pragma unroll
            for (int i = 0; i < 2; i++) {
                float2 p0 = *(const float2*)(As + (wm + i * 16 + g) * GST + kc);
                float2 p1 = *(const float2*)(As + (wm + i * 16 + g + 8) * GST + kc);
                af[i][0] = __float_as_uint(p0.x);
                af[i][1] = __float_as_uint(p1.x);
                af[i][2] = __float_as_uint(p0.y);
                af[i][3] = __float_as_uint(p1.y);
            }
            #pragma unroll
            for (int j = 0; j < 8; j++) {
                float2 pb = *(const float2*)(Ws + (wn + j * 8 + g) * GST + kc);
                unsigned bf[2] = { __float_as_uint(pb.x), __float_as_uint(pb.y) };
                mma_tf32(acc[0][j], af[0], bf);
                mma_tf32(acc[1][j], af[1], bf);
            }
        }

        if (more) {
            const int ob = buf ^ 1;
            #pragma unroll
            for (int m = 0; m < 2; m++) {
                float* da = sm + (size_t)(ob * 128 + r0 + 64 * m) * GST + kg * 8;
                float* dw = sm + (size_t)((2 + ob) * 128 + r0 + 64 * m) * GST + kg * 8;
                float4 lo = make_float4(tf32r(ra[m][0].x), tf32r(ra[m][1].x),
                                        tf32r(ra[m][0].y), tf32r(ra[m][1].y));
                float4 hi = make_float4(tf32r(ra[m][0].z), tf32r(ra[m][1].z),
                                        tf32r(ra[m][0].w), tf32r(ra[m][1].w));
                *(float4*)da = lo; *(float4*)(da + 4) = hi;
                lo = make_float4(tf32r(rw[m][0].x), tf32r(rw[m][1].x),
                                tf32r(rw[m][0].y), tf32r(rw[m][1].y));
                hi = make_float4(tf32r(rw[m][0].z), tf32r(rw[m][1].z),
                                tf32r(rw[m][0].w), tf32r(rw[m][1].w));
                *(float4*)dw = lo; *(float4*)(dw + 4) = hi;
            }
        }
        __syncthreads();
        buf ^= 1;
    }

    // Epilogue: acc[i][j] rows (wm+16i+g / +8), cols (wn+8j+2t / +1)
    #pragma unroll
    for (int i = 0; i < 2; i++) {
        #pragma unroll
        for (int j = 0; j < 8; j++) {
            int mrow = m0 + wm + i * 16 + g;
            int ncol = n0 + wn + j * 8 + t * 2;
            float b0 = bias[ncol], b1 = bias[ncol + 1];
            float2 lo = make_float2(acc[i][j][0] + b0, acc[i][j][1] + b1);
            float2 hi = make_float2(acc[i][j][2] + b0, acc[i][j][3] + b1);
            if (head_major) {
                int hh = ncol >> 6, hd = ncol & 63;
                size_t a0 = ((((size_t)(mrow >> 11) * Hq + hh) << 11)
                             + (mrow & 2047)) * HDq + hd;
                int mr2 = mrow + 8;
                size_t a1 = ((((size_t)(mr2 >> 11) * Hq + hh) << 11)
                             + (mr2 & 2047)) * HDq + hd;
                *(float2*)(C + a0) = lo;
                *(float2*)(C + a1) = hi;
            } else {
                *(float2*)(C + (size_t)mrow * GK + ncol) = lo;
                *(float2*)(C + (size_t)(mrow + 8) * GK + ncol) = hi;
            }
        }
    }
}

// ===========================================================================
// TF32 flash attention, 128 queries/block, 4 warps x 32 rows (2 x m16),
// 64-key tiles. K stored column-pair-interleaved (LDS.64 B-frags),
// V plain [key][hd] (conflict-free scalar B-frags), P per-warp in smem.
// ===========================================================================
#define KST 72
#define PST 68
#define ATTN_SMEM ((2 * 64 * KST + 128 * PST) * 4)

__global__ __launch_bounds__(128) void attn_mma()
{
    extern __shared__ float sm[];
    float* Ks = sm;                       // [64][KST] interleaved cols (hd)
    float* Vs = sm + 64 * KST;            // [64][KST] plain [key][hd]
    float* Ps = sm + 2 * 64 * KST;        // [128][PST]: Q staging, then P

    const int bh   = blockIdx.y;          // 0..31
    const int q0   = blockIdx.x * 128;
    const int b    = bh >> 4;
    const int h    = bh & 15;
    const int tid  = threadIdx.x;
    const int warp = tid >> 5;
    const int lane = tid & 31;
    const int g    = lane >> 2;
    const int t    = lane & 3;
    const int wm   = warp * 32;

    const float* gq = g_q + (((size_t)bh) << 11) * HDq;
    const float* gk = g_k + (((size_t)bh) << 11) * HDq;
    const float* gv = g_v + (((size_t)bh) << 11) * HDq;

    // ---- Stage Q (scaled 0.125, tf32, interleaved cols) into Ps ----
    #pragma unroll
    for (int m = 0; m < 8; m++) {
        int task = tid + m * 128;         // 0..1023
        int r = task >> 3, kgq = task & 7;
        const float* src = gq + (size_t)(q0 + r) * HDq + kgq * 8;
        float4 v0 = *(const float4*)src;
        float4 v1 = *(const float4*)(src + 4);
        float* dst = Ps + r * PST + kgq * 8;
        *(float4*)dst = make_float4(tf32r(v0.x * 0.125f), tf32r(v1.x * 0.125f),
                                    tf32r(v0.y * 0.125f), tf32r(v1.y * 0.125f));
        *(float4*)(dst + 4) = make_float4(tf32r(v0.z * 0.125f), tf32r(v1.z * 0.125f),
                                          tf32r(v0.w * 0.125f), tf32r(v1.w * 0.125f));
    }
    __syncthreads();

    unsigned qa[2][8][4];
    #pragma unroll
    for (int i = 0; i < 2; i++)
        #pragma unroll
        for (int k = 0; k < 8; k++) {
            float2 p0 = *(const float2*)(Ps + (wm + i * 16 + g) * PST + k * 8 + 2 * t);
            float2 p1 = *(const float2*)(Ps + (wm + i * 16 + g + 8) * PST + k * 8 + 2 * t);
            qa[i][k][0] = __float_as_uint(p0.x);
            qa[i][k][1] = __float_as_uint(p1.x);
            qa[i][k][2] = __float_as_uint(p0.y);
            qa[i][k][3] = __float_as_uint(p1.y);
        }
    __syncthreads();

    float oacc[2][8][4] = {};
    float mrow[2][2] = { {-1e30f, -1e30f}, {-1e30f, -1e30f} };
    float lrow[2][2] = { {0.f, 0.f}, {0.f, 0.f} };

    for (int tile = 0; tile < Sq / 64; tile++) {
        // ---- Stage K (interleaved) ----
        #pragma unroll
        for (int m = 0; m < 4; m++) {
            int task = tid + m * 128;     // 0..511
            int r = task >> 3, kgq = task & 7;
            const float* src = gk + (size_t)(tile * 64 + r) * HDq + kgq * 8;
            float4 v0 = *(const float4*)src;
            float4 v1 = *(const float4*)(src + 4);
            float* dst = Ks + r * KST + kgq * 8;
            *(float4*)dst = make_float4(tf32r(v0.x), tf32r(v1.x),
                                        tf32r(v0.y), tf32r(v1.y));
            *(float4*)(dst + 4) = make_float4(tf32r(v0.z), tf32r(v1.z),
                                              tf32r(v0.w), tf32r(v1.w));
        }
        // ---- Stage V (plain) ----
        #pragma unroll
        for (int m = 0; m < 8; m++) {
            int idx = tid + m * 128;      // 0..1023 float4s
            int r = idx >> 4, c = (idx & 15) * 4;
            float4 v = *(const float4*)(gv + (size_t)(tile * 64 + r) * HDq + c);
            *(float4*)(Vs + r * KST + c) =
                make_float4(tf32r(v.x), tf32r(v.y), tf32r(v.z), tf32r(v.w));
        }
        __syncthreads();

        // ---- S = Q K^T : 128 mma, B-frags reused across both m-tiles ----
        float sacc[2][8][4] = {};
        #pragma unroll
        for (int k = 0; k < 8; k++) {
            #pragma unroll
            for (int j = 0; j < 8; j++) {
                float2 pb = *(const float2*)(Ks + (j * 8 + g) * KST + k * 8 + 2 * t);
                unsigned bf[2] = { __float_as_uint(pb.x), __float_as_uint(pb.y) };
                mma_tf32(sacc[0][j], qa[0][k], bf);
                mma_tf32(sacc[1][j], qa[1][k], bf);
            }
        }

        // ---- Online softmax (per m-tile i) ----
        #pragma unroll
        for (int i = 0; i < 2; i++) {
            float mx0 = -1e30f, mx1 = -1e30f;
            #pragma unroll
            for (int j = 0; j < 8; j++) {
                mx0 = fmaxf(mx0, fmaxf(sacc[i][j][0], sacc[i][j][1]));
                mx1 = fmaxf(mx1, fmaxf(sacc[i][j][2], sacc[i][j][3]));
            }
            mx0 = fmaxf(mx0, __shfl_xor_sync(0xffffffffu, mx0, 1));
            mx0 = fmaxf(mx0, __shfl_xor_sync(0xffffffffu, mx0, 2));
            mx1 = fmaxf(mx1, __shfl_xor_sync(0xffffffffu, mx1, 1));
            mx1 = fmaxf(mx1, __shfl_xor_sync(0xffffffffu, mx1, 2));

            float nm0 = fmaxf(mrow[i][0], mx0), nm1 = fmaxf(mrow[i][1], mx1);
            float a0 = __expf(mrow[i][0] - nm0), a1 = __expf(mrow[i][1] - nm1);
            mrow[i][0] = nm0; mrow[i][1] = nm1;

            float ps0 = 0.f, ps1 = 0.f;
            #pragma unroll
            for (int j = 0; j < 8; j++) {
                sacc[i][j][0] = __expf(sacc[i][j][0] - nm0);
                sacc[i][j][1] = __expf(sacc[i][j][1] - nm0);
                sacc[i][j][2] = __expf(sacc[i][j][2] - nm1);
                sacc[i][j][3] = __expf(sacc[i][j][3] - nm1);
                ps0 += sacc[i][j][0] + sacc[i][j][1];
                ps1 += sacc[i][j][2] + sacc[i][j][3];
            }
            ps0 += __shfl_xor_sync(0xffffffffu, ps0, 1);
            ps0 += __shfl_xor_sync(0xffffffffu, ps0, 2);
            ps1 += __shfl_xor_sync(0xffffffffu, ps1, 1);
            ps1 += __shfl_xor_sync(0xffffffffu, ps1, 2);
            lrow[i][0] = lrow[i][0] * a0 + ps0;
            lrow[i][1] = lrow[i][1] * a1 + ps1;

            #pragma unroll
            for (int j = 0; j < 8; j++) {
                oacc[i][j][0] *= a0; oacc[i][j][1] *= a0;
                oacc[i][j][2] *= a1; oacc[i][j][3] *= a1;
            }
        }

        // ---- Store P (tf32) into Ps (warp-private rows) ----
        #pragma unroll
        for (int i = 0; i < 2; i++)
            #pragma unroll
            for (int j = 0; j < 8; j++) {
                *(float2*)(Ps + (wm + i * 16 + g) * PST + j * 8 + 2 * t) =
                    make_float2(tf32r(sacc[i][j][0]), tf32r(sacc[i][j][1]));
                *(float2*)(Ps + (wm + i * 16 + g + 8) * PST + j * 8 + 2 * t) =
                    make_float2(tf32r(sacc[i][j][2]), tf32r(sacc[i][j][3]));
            }
        __syncwarp();

        // ---- O += P V : 128 mma ----
        #pragma unroll
        for (int k = 0; k < 8; k++) {
            unsigned pa[2][4];
            #pragma unroll
            for (int i = 0; i < 2; i++) {
                const float* pr0 = Ps + (wm + i * 16 + g) * PST + k * 8;
                const float* pr1 = Ps + (wm + i * 16 + g + 8) * PST + k * 8;
                pa[i][0] = __float_as_uint(pr0[t]);
                pa[i][1] = __float_as_uint(pr1[t]);
                pa[i][2] = __float_as_uint(pr0[t + 4]);
                pa[i][3] = __float_as_uint(pr1[t + 4]);
            }
            #pragma unroll
            for (int j = 0; j < 8; j++) {
                unsigned bf[2] = {
                    __float_as_uint(Vs[(k * 8 + t) * KST + j * 8 + g]),
                    __float_as_uint(Vs[(k * 8 + t + 4) * KST + j * 8 + g]) };
                mma_tf32(oacc[0][j], pa[0], bf);
                mma_tf32(oacc[1][j], pa[1], bf);
            }
        }
        __syncthreads();
    }

    // ---- Epilogue ----
    #pragma unroll
    for (int i = 0; i < 2; i++) {
        float il0 = 1.0f / lrow[i][0], il1 = 1.0f / lrow[i][1];
        #pragma unroll
        for (int j = 0; j < 8; j++) {
            int r = q0 + wm + i * 16 + g;
            int col = h * HDq + j * 8 + 2 * t;
            size_t a0 = (size_t)(b * Sq + r) * Dq + col;
            size_t a1 = (size_t)(b * Sq + r + 8) * Dq + col;
            *(float2*)(g_att + a0) =
                make_float2(oacc[i][j][0] * il0, oacc[i][j][1] * il0);
            *(float2*)(g_att + a1) =
                make_float2(oacc[i][j][2] * il1, oacc[i][j][3] * il1);
        }
    }
}

// ---------------------------------------------------------------------------
// Launch.  Input order: xq, xv, xk, Wq, bq, Wk, bk, Wv, bv, Wo, bo
// ---------------------------------------------------------------------------
extern "C" void kernel_launch(void* const* d_in, const int* in_sizes, int n_in,
                              void* d_out, int out_size)
{
    const float* xq = (const float*)d_in[0];
    const float* xv = (const float*)d_in[1];
    const float* xk = (const float*)d_in[2];
    const float* Wq = (const float*)d_in[3];
    const float* bq = (const float*)d_in[4];
    const float* Wk = (const float*)d_in[5];
    const float* bk = (const float*)d_in[6];
    const float* Wv = (const float*)d_in[7];
    const float* bv = (const float*)d_in[8];
    const float* Wo = (const float*)d_in[9];
    const float* bo = (const float*)d_in[10];
    float* out = (float*)d_out;

    float *pq, *pk, *pv, *patt;
    cudaGetSymbolAddress((void**)&pq, g_q);
    cudaGetSymbolAddress((void**)&pk, g_k);
    cudaGetSymbolAddress((void**)&pv, g_v);
    cudaGetSymbolAddress((void**)&patt, g_att);

    static int attr_done = 0;
    if (!attr_done) {
        cudaFuncSetAttribute(gemm_tf32,
            cudaFuncAttributeMaxDynamicSharedMemorySize, GEMM_SMEM);
        cudaFuncSetAttribute(attn_mma,
            cudaFuncAttributeMaxDynamicSharedMemorySize, ATTN_SMEM);
        attr_done = 1;
    }

    // Fused Q/K/V projections
    dim3 gqkv(Dq / 128, Mq / 128, 3);     // (8, 32, 3)
    gemm_tf32<<<gqkv, 256, GEMM_SMEM>>>(
        xq, Wq, bq, pq,
        xk, Wk, bk, pk,
        xv, Wv, bv, pv, 1);

    dim3 gattn(Sq / 128, Bq * Hq);        // (16, 32)
    attn_mma<<<gattn, 128, ATTN_SMEM>>>();

    dim3 gproj(Dq / 128, Mq / 128, 1);    // (8, 32)
    gemm_tf32<<<gproj, 256, GEMM_SMEM>>>(
        patt, Wo, bo, out,
        patt, Wo, bo, out,
        patt, Wo, bo, out, 0);
}